// round 1
// baseline (speedup 1.0000x reference)
#include <cuda_runtime.h>

// Problem: 4-qubit / 2-layer StronglyEntanglingLayers over 2x2 patches.
// x: (32,224,224,1) f32, weights: (2,4,3) f32 -> out: (32,112,112,4) f32.

#define NB   32
#define IH   224
#define IW   224
#define OH   112
#define OW   112
#define NPATCH (NB * OH * OW)   // 401408 = 1568 * 256 exactly

#define THREADS 256

__device__ __forceinline__ float2 cmul(float2 a, float2 b) {
    return make_float2(fmaf(a.x, b.x, -a.y * b.y), fmaf(a.x, b.y, a.y * b.x));
}

__global__ __launch_bounds__(THREADS)
void qip_kernel(const float* __restrict__ x,
                const float* __restrict__ weights,
                float* __restrict__ out)
{
    // ---- per-block precompute of the 8 Rot(phi,theta,omega) 2x2 matrices ----
    // g[l*4+w][0..3] = {g00, g01, g10, g11}
    __shared__ float2 gmat[8][4];
    int t = threadIdx.x;
    if (t < 8) {
        int l = t >> 2, w = t & 3;
        const float* ww = weights + (l * 4 + w) * 3;
        float phi = ww[0], th = ww[1], om = ww[2];
        float c, s;
        sincosf(0.5f * th, &s, &c);
        float pa = 0.5f * (phi + om);
        float ma = 0.5f * (phi - om);
        float cp, sp, cm, sm;
        sincosf(pa, &sp, &cp);
        sincosf(ma, &sm, &cm);
        // ep = (cp, -sp), em = (cm, -sm)
        gmat[t][0] = make_float2(cp * c, -sp * c);    // ep * c
        gmat[t][1] = make_float2(-cm * s, -sm * s);   // -conj(em) * s
        gmat[t][2] = make_float2(cm * s, -sm * s);    // em * s
        gmat[t][3] = make_float2(cp * c, sp * c);     // conj(ep) * c
    }
    __syncthreads();

    int p = blockIdx.x * blockDim.x + threadIdx.x;
    if (p >= NPATCH) return;

    int ow  = p % OW;
    int tmp = p / OW;
    int oh  = tmp % OH;
    int b   = tmp / OH;

    // 2x2 patch: rows (2*oh, 2*oh+1), cols (2*ow, 2*ow+1). Coalesced float2 loads.
    const float* base = x + ((size_t)(b * IH + 2 * oh) * IW + 2 * ow);
    float2 r0 = *(const float2*)(base);
    float2 r1 = *(const float2*)(base + IW);

    float px[4] = { r0.x, r0.y, r1.x, r1.y };  // wires 0..3 (wire 0 = MSB)

    // ---- encoding: per-wire state after RY(a)RX(a)|0>, a = px*pi ----
    // half = a/2; v0 = c^2 + i s^2 ; v1 = s*c - i c*s = sc*(1 - i)
    float2 v[4][2];
#pragma unroll
    for (int w = 0; w < 4; w++) {
        float hs, hc;
        __sincosf(px[w] * 1.57079632679489662f, &hs, &hc);
        v[w][0] = make_float2(hc * hc, hs * hs);
        float sc = hs * hc;
        v[w][1] = make_float2(sc, -sc);
    }

    // ---- build product state psi[16], index i = (w0<<3)|(w1<<2)|(w2<<1)|w3 ----
    float2 t01[4], t23[4];
#pragma unroll
    for (int i = 0; i < 4; i++) t01[i] = cmul(v[0][i >> 1], v[1][i & 1]);
#pragma unroll
    for (int i = 0; i < 4; i++) t23[i] = cmul(v[2][i >> 1], v[3][i & 1]);

    float2 psi[16];
#pragma unroll
    for (int i = 0; i < 16; i++) psi[i] = cmul(t01[i >> 2], t23[i & 3]);

    // ---- 2 layers: 4 Rot gates then 4 CNOTs (ranges r = 1, then 2) ----
#pragma unroll
    for (int l = 0; l < 2; l++) {
#pragma unroll
        for (int w = 0; w < 4; w++) {
            float2 g00 = gmat[l * 4 + w][0];
            float2 g01 = gmat[l * 4 + w][1];
            float2 g10 = gmat[l * 4 + w][2];
            float2 g11 = gmat[l * 4 + w][3];
            int m = 1 << (3 - w);
#pragma unroll
            for (int i = 0; i < 16; i++) {
                if ((i & m) == 0) {
                    float2 a  = psi[i];
                    float2 bb = psi[i | m];
                    float re0 = fmaf(g00.x, a.x, fmaf(-g00.y, a.y, fmaf(g01.x, bb.x, -g01.y * bb.y)));
                    float im0 = fmaf(g00.x, a.y, fmaf( g00.y, a.x, fmaf(g01.x, bb.y,  g01.y * bb.x)));
                    float re1 = fmaf(g10.x, a.x, fmaf(-g10.y, a.y, fmaf(g11.x, bb.x, -g11.y * bb.y)));
                    float im1 = fmaf(g10.x, a.y, fmaf( g10.y, a.x, fmaf(g11.x, bb.y,  g11.y * bb.x)));
                    psi[i]     = make_float2(re0, im0);
                    psi[i | m] = make_float2(re1, im1);
                }
            }
        }
        int r = (l == 0) ? 1 : 2;
#pragma unroll
        for (int w = 0; w < 4; w++) {
            int ctrl = w;
            int tgt  = (w + r) & 3;
            int cm = 1 << (3 - ctrl);
            int tm = 1 << (3 - tgt);
#pragma unroll
            for (int i = 0; i < 16; i++) {
                if ((i & cm) && !(i & tm)) {
                    float2 a = psi[i];
                    psi[i] = psi[i | tm];
                    psi[i | tm] = a;
                }
            }
        }
    }

    // ---- probabilities and PauliZ expvals ----
    float pr[16];
#pragma unroll
    for (int i = 0; i < 16; i++) pr[i] = fmaf(psi[i].x, psi[i].x, psi[i].y * psi[i].y);

    float4 e;
    float ev[4];
#pragma unroll
    for (int k = 0; k < 4; k++) {
        int m = 1 << (3 - k);
        float s = 0.f;
#pragma unroll
        for (int i = 0; i < 16; i++) s += (i & m) ? -pr[i] : pr[i];
        ev[k] = s;
    }
    e.x = ev[0]; e.y = ev[1]; e.z = ev[2]; e.w = ev[3];

    // out[b][oh][ow][k] -> float4 at index p
    ((float4*)out)[p] = e;
}

extern "C" void kernel_launch(void* const* d_in, const int* in_sizes, int n_in,
                              void* d_out, int out_size) {
    const float* x = (const float*)d_in[0];
    const float* w = (const float*)d_in[1];
    float* out = (float*)d_out;
    qip_kernel<<<NPATCH / THREADS, THREADS>>>(x, w, out);
}

// round 2
// speedup vs baseline: 2.7774x; 2.7774x over previous
#include <cuda_runtime.h>

// QuantumImagePreprocessor: 4-qubit / 2-layer StronglyEntanglingLayers over 2x2 patches.
// Heisenberg-picture reformulation: E_k = sum over <=9 signed Pauli-string terms of
// products of per-wire Bloch components. No state vector.
//
// x: (32,224,224,1) f32, weights: (2,4,3) f32 -> out: (32,112,112,4) f32.

#define NB   32
#define IH   224
#define IW   224
#define OH   112
#define OW   112
#define NPATCH (NB * OH * OW)   // 401408 = 1568 * 256

#define THREADS 256
#define PI_F 3.14159265358979323846f

__global__ __launch_bounds__(THREADS)
void qip_kernel(const float* __restrict__ x,
                const float* __restrict__ weights,
                float* __restrict__ out)
{
    // ---------------- per-block coefficient precompute ----------------
    // S1[w]: 3x3 Bloch rotation of layer-1 Rot on wire w (rows padded to float4)
    // A[w]:  z-row of layer-2 Rot's Bloch rotation (R2† Z R2 = A·sigma)
    // sC[0]    = C0 (3 coefs for E0)
    // sC[1]    = C1 (3 signed coefs for E1)
    // sC[2..4] = C2 (9 signed coefs for E2; [2].xyzw=c0..3, [3].xyzw=c4..7, [4].x=c8)
    // sC[5..7] = C3 (9 signed coefs for E3)
    __shared__ float4 sS1[4][3];
    __shared__ float4 sC[8];
    __shared__ float  sA[4][3];

    int t = threadIdx.x;
    if (t < 8) {
        int l = t >> 2, w = t & 3;
        const float* ww = weights + (l * 4 + w) * 3;
        float phi = ww[0], th = ww[1], om = ww[2];
        float sf, cf, st, ct, so, co;
        sincosf(phi, &sf, &cf);
        sincosf(th,  &st, &ct);
        sincosf(om,  &so, &co);
        // S = Sz(om) * Sy(th) * Sz(phi)
        // M = Sy(th)*Sz(phi) = [[ct*cf, -ct*sf, st],[sf, cf, 0],[-st*cf, st*sf, ct]]
        float M00 = ct * cf, M01 = -ct * sf, M02 = st;
        float M10 = sf,      M11 = cf,       M12 = 0.f;
        float M20 = -st * cf, M21 = st * sf, M22 = ct;
        if (l == 0) {
            // rows of S = Sz(om) * M
            sS1[w][0] = make_float4(co * M00 - so * M10, co * M01 - so * M11, co * M02 - so * M12, 0.f);
            sS1[w][1] = make_float4(so * M00 + co * M10, so * M01 + co * M11, so * M02 + co * M12, 0.f);
            sS1[w][2] = make_float4(M20, M21, M22, 0.f);
        } else {
            // z-row of S (row 2 = M row 2, unaffected by Sz(om))
            sA[w][0] = M20; sA[w][1] = M21; sA[w][2] = M22;
        }
    }
    __syncthreads();
    if (t == 0) {
        float a0x = sA[0][0], a0y = sA[0][1], a0z = sA[0][2];
        float a1x = sA[1][0], a1y = sA[1][1], a1z = sA[1][2];
        float a2x = sA[2][0], a2y = sA[2][1], a2z = sA[2][2];
        float a3x = sA[3][0], a3y = sA[3][1], a3z = sA[3][2];
        sC[0] = make_float4(a2x, a2y, a2z, 0.f);
        sC[1] = make_float4(a3x, -a3y, a3z, 0.f);
        // E2 coefs c_ij = sgn * a0_i * a2_j, sgn rows: {+,-,-},{-,+,+},{-,+,+}
        sC[2] = make_float4( a0x * a2x, -a0x * a2y, -a0x * a2z, -a0y * a2x);
        sC[3] = make_float4( a0y * a2y,  a0y * a2z, -a0z * a2x,  a0z * a2y);
        sC[4] = make_float4( a0z * a2z, 0.f, 0.f, 0.f);
        // E3 coefs d_ij = sgn * a1_i * a3_j, sgn rows: {+,-,-},{+,+,+},{-,+,+}
        sC[5] = make_float4( a1x * a3x, -a1x * a3y, -a1x * a3z,  a1y * a3x);
        sC[6] = make_float4( a1y * a3y,  a1y * a3z, -a1z * a3x,  a1z * a3y);
        sC[7] = make_float4( a1z * a3z, 0.f, 0.f, 0.f);
    }
    __syncthreads();

    int p = blockIdx.x * blockDim.x + threadIdx.x;
    if (p >= NPATCH) return;

    int ow  = p % OW;
    int tmp = p / OW;
    int oh  = tmp % OH;
    int b   = tmp / OH;

    const float* base = x + ((size_t)(b * IH + 2 * oh) * IW + 2 * ow);
    float2 r0 = *(const float2*)(base);
    float2 r1 = *(const float2*)(base + IW);
    float px[4] = { r0.x, r0.y, r1.x, r1.y };   // wires 0..3

    // ---- per-wire Bloch vectors: n = (sin a * cos a, -sin a, cos^2 a), a = px*pi ----
    // then m_w = S1_w * n_w
    float mx[4], my[4], mz[4];
#pragma unroll
    for (int w = 0; w < 4; w++) {
        float s, c;
        __sincosf(px[w] * PI_F, &s, &c);
        float n0 = s * c;
        float n1 = -s;
        float n2 = c * c;
        float4 q0 = sS1[w][0];
        float4 q1 = sS1[w][1];
        float4 q2 = sS1[w][2];
        mx[w] = fmaf(q0.x, n0, fmaf(q0.y, n1, q0.z * n2));
        my[w] = fmaf(q1.x, n0, fmaf(q1.y, n1, q1.z * n2));
        mz[w] = fmaf(q2.x, n0, fmaf(q2.y, n1, q2.z * n2));
    }

    // shared pair products
    float xx01 = mx[0] * mx[1];
    float yy01 = my[0] * my[1];
    float zz01 = mz[0] * mz[1];

    float4 c0 = sC[0];
    float4 c1 = sC[1];

    // E0 = a2x*(m2x m3x) + a2y*(m0z m1z m2y m3x) + a2z*(m0z m1z m2z)
    float E0 = c0.x * (mx[2] * mx[3])
             + c0.y * (zz01 * my[2] * mx[3])
             + c0.z * (zz01 * mz[2]);

    // E1 = a3x*(m0x m1x m3x) - a3y*(m0y m1y m2z m3y) + a3z*(m0z m1z m2z m3z)
    float E1 = c1.x * (xx01 * mx[3])
             + c1.y * (yy01 * mz[2] * my[3])
             + c1.z * (zz01 * mz[2] * mz[3]);

    float4 c2a = sC[2];
    float4 c2b = sC[3];
    float4 c2c = sC[4];

    // E2 terms (signs folded into coefs):
    //  c00 (m0x m1x m2x m3x)  c01 (m0y m1y m2y m3x)  c02 (m0y m1y m2z)
    //  c10 (m0x m1y m2y m3y)  c11 (m0y m1x m2x m3y)  c12 (m0y m1x m3z)
    //  c20 (m1z m2y m3y)      c21 (m0z m2x m3y)      c22 (m0z m3z)
    float E2 = c2a.x * (xx01 * mx[2] * mx[3])
             + c2a.y * (yy01 * my[2] * mx[3])
             + c2a.z * (yy01 * mz[2])
             + c2a.w * (mx[0] * my[1] * my[2] * my[3])
             + c2b.x * (my[0] * mx[1] * mx[2] * my[3])
             + c2b.y * (my[0] * mx[1] * mz[3])
             + c2b.z * (mz[1] * my[2] * my[3])
             + c2b.w * (mz[0] * mx[2] * my[3])
             + c2c.x * (mz[0] * mz[3]);

    float4 c3a = sC[5];
    float4 c3b = sC[6];
    float4 c3c = sC[7];

    // E3 terms:
    //  d00 (m0x m2x m3x)       d01 (m0y m1z m2y m3y)  d02 (m0z m1y m2y m3z)
    //  d10 (m0y m1z m2x m3x)   d11 (m0x m2y m3y)      d12 (m1x m2y m3z)
    //  d20 (m0y m1y m3x)       d21 (m0x m1x m2z m3y)  d22 (m2z m3z)
    float E3 = c3a.x * (mx[0] * mx[2] * mx[3])
             + c3a.y * (my[0] * mz[1] * my[2] * my[3])
             + c3a.z * (mz[0] * my[1] * my[2] * mz[3])
             + c3a.w * (my[0] * mz[1] * mx[2] * mx[3])
             + c3b.x * (mx[0] * my[2] * my[3])
             + c3b.y * (mx[1] * my[2] * mz[3])
             + c3b.z * (yy01 * mx[3])
             + c3b.w * (xx01 * mz[2] * my[3])
             + c3c.x * (mz[2] * mz[3]);

    ((float4*)out)[p] = make_float4(E0, E1, E2, E3);
}

extern "C" void kernel_launch(void* const* d_in, const int* in_sizes, int n_in,
                              void* d_out, int out_size) {
    const float* x = (const float*)d_in[0];
    const float* w = (const float*)d_in[1];
    float* out = (float*)d_out;
    qip_kernel<<<NPATCH / THREADS, THREADS>>>(x, w, out);
}

// round 3
// speedup vs baseline: 2.8273x; 1.0180x over previous
#include <cuda_runtime.h>

// QuantumImagePreprocessor: Heisenberg-picture closed form.
// x: (32,224,224,1) f32, weights: (2,4,3) f32 -> out: (32,112,112,4) f32.
// Each thread computes 2 patches (p and p + NPATCH/2) -> grid fits in ONE wave.

#define NB   32
#define IH   224
#define IW   224
#define OH   112
#define OW   112
#define NPATCH (NB * OH * OW)        // 401408
#define HALF   (NPATCH / 2)          // 200704
#define BOFF   (16 * IH * IW)        // element offset: batch + 16

#define THREADS 256
#define PI_F 3.14159265358979323846f

__global__ __launch_bounds__(THREADS, 6)
void qip_kernel(const float* __restrict__ x,
                const float* __restrict__ weights,
                float* __restrict__ out)
{
    // S1[w] rows (column 1 pre-negated so n1 = +sin), coefficient packs sC[0..7].
    __shared__ float4 sS1[4][3];
    __shared__ float4 sC[8];

    int t = threadIdx.x;
    if (t < 4) {
        const float* ww = weights + t * 3;
        float sf, cf, st, ct, so, co;
        __sincosf(ww[0], &sf, &cf);
        __sincosf(ww[1], &st, &ct);
        __sincosf(ww[2], &so, &co);
        float M00 = ct * cf, M01 = -ct * sf, M02 = st;
        float M10 = sf,      M11 = cf;
        float M20 = -st * cf, M21 = st * sf, M22 = ct;
        // rows of S = Sz(om)*M, with column 1 negated (absorbs n1 = -s)
        sS1[t][0] = make_float4(co * M00 - so * M10, -(co * M01 - so * M11), co * M02, 0.f);
        sS1[t][1] = make_float4(so * M00 + co * M10, -(so * M01 + co * M11), so * M02, 0.f);
        sS1[t][2] = make_float4(M20, -M21, M22, 0.f);
    } else if (t == 4 || t == 5) {
        // A_w = z-row of layer-2 Bloch rotation = (-st*cf, st*sf, ct)
        int wA = t - 4;          // 0 or 1
        int wB = wA + 2;         // 2 or 3
        const float* wa = weights + 12 + wA * 3;
        const float* wb = weights + 12 + wB * 3;
        float sfa, cfa, sta, cta, sfb, cfb, stb, ctb;
        __sincosf(wa[0], &sfa, &cfa);
        __sincosf(wa[1], &sta, &cta);
        __sincosf(wb[0], &sfb, &cfb);
        __sincosf(wb[1], &stb, &ctb);
        float ax = -sta * cfa, ay = sta * sfa, az = cta;   // a0 or a1
        float bx = -stb * cfb, by = stb * sfb, bz = ctb;   // a2 or a3
        if (t == 4) {
            sC[0] = make_float4(bx, by, bz, 0.f);
            sC[2] = make_float4( ax * bx, -ax * by, -ax * bz, -ay * bx);
            sC[3] = make_float4( ay * by,  ay * bz, -az * bx,  az * by);
            sC[4] = make_float4( az * bz, 0.f, 0.f, 0.f);
        } else {
            sC[1] = make_float4(bx, -by, bz, 0.f);
            sC[5] = make_float4( ax * bx, -ax * by, -ax * bz,  ay * bx);
            sC[6] = make_float4( ay * by,  ay * bz, -az * bx,  az * by);
            sC[7] = make_float4( az * bz, 0.f, 0.f, 0.f);
        }
    }
    __syncthreads();

    int p0 = blockIdx.x * blockDim.x + t;   // 0 .. HALF-1

    int ow  = p0 % OW;
    int tmp = p0 / OW;
    int oh  = tmp % OH;
    int b   = tmp / OH;

    const float* base = x + ((size_t)(b * IH + 2 * oh) * IW + 2 * ow);
    // front-batch all 4 loads (MLP=4)
    float2 r0a = *(const float2*)(base);
    float2 r1a = *(const float2*)(base + IW);
    float2 r0b = *(const float2*)(base + BOFF);
    float2 r1b = *(const float2*)(base + BOFF + IW);

    float px[2][4] = { { r0a.x, r0a.y, r1a.x, r1a.y },
                       { r0b.x, r0b.y, r1b.x, r1b.y } };

    float mx[2][4], my[2][4], mz[2][4];
#pragma unroll
    for (int w = 0; w < 4; w++) {
        float4 q0 = sS1[w][0];
        float4 q1 = sS1[w][1];
        float4 q2 = sS1[w][2];
#pragma unroll
        for (int pp = 0; pp < 2; pp++) {
            float s, c;
            __sincosf(px[pp][w] * PI_F, &s, &c);
            float n0 = s * c;
            float n2 = c * c;
            mx[pp][w] = fmaf(q0.x, n0, fmaf(q0.y, s, q0.z * n2));
            my[pp][w] = fmaf(q1.x, n0, fmaf(q1.y, s, q1.z * n2));
            mz[pp][w] = fmaf(q2.x, n0, fmaf(q2.y, s, q2.z * n2));
        }
    }

    float4 c0  = sC[0];
    float4 c1  = sC[1];
    float4 c2a = sC[2];
    float4 c2b = sC[3];
    float4 c2c = sC[4];
    float4 c3a = sC[5];
    float4 c3b = sC[6];
    float4 c3c = sC[7];

    float4 res[2];
#pragma unroll
    for (int pp = 0; pp < 2; pp++) {
        float m0x = mx[pp][0], m0y = my[pp][0], m0z = mz[pp][0];
        float m1x = mx[pp][1], m1y = my[pp][1], m1z = mz[pp][1];
        float m2x = mx[pp][2], m2y = my[pp][2], m2z = mz[pp][2];
        float m3x = mx[pp][3], m3y = my[pp][3], m3z = mz[pp][3];

        float xx01 = m0x * m1x;
        float yy01 = m0y * m1y;
        float zz01 = m0z * m1z;

        float E0 = c0.x * (m2x * m3x)
                 + c0.y * (zz01 * m2y * m3x)
                 + c0.z * (zz01 * m2z);

        float E1 = c1.x * (xx01 * m3x)
                 + c1.y * (yy01 * m2z * m3y)
                 + c1.z * (zz01 * m2z * m3z);

        float E2 = c2a.x * (xx01 * m2x * m3x)
                 + c2a.y * (yy01 * m2y * m3x)
                 + c2a.z * (yy01 * m2z)
                 + c2a.w * (m0x * m1y * m2y * m3y)
                 + c2b.x * (m0y * m1x * m2x * m3y)
                 + c2b.y * (m0y * m1x * m3z)
                 + c2b.z * (m1z * m2y * m3y)
                 + c2b.w * (m0z * m2x * m3y)
                 + c2c.x * (m0z * m3z);

        float E3 = c3a.x * (m0x * m2x * m3x)
                 + c3a.y * (m0y * m1z * m2y * m3y)
                 + c3a.z * (m0z * m1y * m2y * m3z)
                 + c3a.w * (m0y * m1z * m2x * m3x)
                 + c3b.x * (m0x * m2y * m3y)
                 + c3b.y * (m1x * m2y * m3z)
                 + c3b.z * (yy01 * m3x)
                 + c3b.w * (xx01 * m2z * m3y)
                 + c3c.x * (m2z * m3z);

        res[pp] = make_float4(E0, E1, E2, E3);
    }

    ((float4*)out)[p0]        = res[0];
    ((float4*)out)[p0 + HALF] = res[1];
}

extern "C" void kernel_launch(void* const* d_in, const int* in_sizes, int n_in,
                              void* d_out, int out_size) {
    const float* x = (const float*)d_in[0];
    const float* w = (const float*)d_in[1];
    float* out = (float*)d_out;
    qip_kernel<<<HALF / THREADS, THREADS>>>(x, w, out);
}